// round 3
// baseline (speedup 1.0000x reference)
#include <cuda_runtime.h>
#include <cstdint>

// x [4,4096,2048] fp32 -> out fp32. R=64.
#define N_TOK    16384
#define D_DIM    2048
#define R_DIM    64
#define TOK_TILE 128
#define DC       64
#define NCHUNK   (D_DIM / DC)
#define EPS      1e-5f
#define THREADS  256

// 96 KB dynamic smem: sX[2][128*64], sW[2][64*64]
#define SX_OFF(b)  ((b) * 8192)
#define SW_OFF(b)  (16384 + (b) * 4096)
#define SMEM_FLOATS 24576
#define SMEM_BYTES  (SMEM_FLOATS * 4)

__device__ float g_C1[R_DIM];            // sum_d gw[r][d]  (tf32-rounded gw)
__device__ float g_C2[R_DIM];            // sum_d beta*w_down + b_down
__device__ float g_gw[R_DIM * D_DIM];    // tf32(gamma[d] * w_down[r][d])

// ---------------- helpers ----------------

__device__ __forceinline__ float to_tf32(float x) {
    unsigned u;
    asm("cvt.rna.tf32.f32 %0, %1;" : "=r"(u) : "f"(x));
    return __uint_as_float(u);
}
__device__ __forceinline__ int swz4(int row, int c4) { return row * 16 + ((c4 + row) & 15); }
__device__ __forceinline__ int swzf(int row, int col) {
    return (row << 6) + ((((col >> 2) + row) & 15) << 2) + (col & 3);
}
__device__ __forceinline__ void mma_tf32(float* c, const unsigned* a, const unsigned* b) {
    asm volatile(
        "mma.sync.aligned.m16n8k8.row.col.f32.tf32.tf32.f32 "
        "{%0,%1,%2,%3}, {%4,%5,%6,%7}, {%8,%9}, {%0,%1,%2,%3};"
        : "+f"(c[0]), "+f"(c[1]), "+f"(c[2]), "+f"(c[3])
        : "r"(a[0]), "r"(a[1]), "r"(a[2]), "r"(a[3]), "r"(b[0]), "r"(b[1]));
}

#define CPA16(dst_u32, src_ptr) \
    asm volatile("cp.async.cg.shared.global [%0], [%1], 16;" :: "r"(dst_u32), "l"(src_ptr))
#define CPC() asm volatile("cp.async.commit_group;")
#define CPW(n) asm volatile("cp.async.wait_group %0;" :: "n"(n))

// ---------------- prep: gw = tf32(gamma*w_down), C1, C2 ----------------

__global__ void prep_kernel(const float* __restrict__ w_down,
                            const float* __restrict__ gamma,
                            const float* __restrict__ beta,
                            const float* __restrict__ b_down) {
    __shared__ float red1[8], red2[8];
    int r = blockIdx.x;
    float s1 = 0.f, s2 = 0.f;
    for (int d = threadIdx.x; d < D_DIM; d += 256) {
        float w = w_down[r * D_DIM + d];
        float gwv = to_tf32(gamma[d] * w);
        g_gw[r * D_DIM + d] = gwv;
        s1 += gwv;
        s2 += beta[d] * w;
    }
    #pragma unroll
    for (int o = 16; o; o >>= 1) {
        s1 += __shfl_down_sync(0xFFFFFFFFu, s1, o);
        s2 += __shfl_down_sync(0xFFFFFFFFu, s2, o);
    }
    if ((threadIdx.x & 31) == 0) { red1[threadIdx.x >> 5] = s1; red2[threadIdx.x >> 5] = s2; }
    __syncthreads();
    if (threadIdx.x == 0) {
        float t1 = 0.f, t2 = 0.f;
        #pragma unroll
        for (int i = 0; i < 8; i++) { t1 += red1[i]; t2 += red2[i]; }
        g_C1[r] = t1;
        g_C2[r] = t2 + b_down[r];
    }
}

// ---------------- main fused kernel ----------------

__global__ __launch_bounds__(THREADS, 1) void adapter_main(
    const float* __restrict__ x,
    const float* __restrict__ w_up,
    const float* __restrict__ b_up,
    const float* __restrict__ scale,
    float* __restrict__ out)
{
    extern __shared__ float smem[];
    const uint32_t sbase = (uint32_t)__cvta_generic_to_shared(smem);

    const int tid  = threadIdx.x;
    const int lane = tid & 31;
    const int wrp  = tid >> 5;
    const int mg   = wrp & 3;
    const int ng   = wrp >> 2;
    const int t0   = blockIdx.x * TOK_TILE;

    const float scaleV = scale[0];

    const float4* __restrict__ xg  = reinterpret_cast<const float4*>(x) + (size_t)t0 * (D_DIM / 4);
    const float4* __restrict__ gwg = reinterpret_cast<const float4*>(g_gw);
    const float4* __restrict__ wug = reinterpret_cast<const float4*>(w_up);

    // per-thread staging coordinates (fixed across chunks)
    // x: 8 slots, (t, c4);  w: 4 slots, (r, c4)
    int xt[8], xc4[8], xdst[8];
    #pragma unroll
    for (int i = 0; i < 8; i++) {
        int idx4 = i * 256 + tid;
        xt[i] = idx4 >> 4; xc4[i] = idx4 & 15;
        xdst[i] = swz4(xt[i], xc4[i]) * 16;
    }
    int wr_[4], wc4[4], wdst[4];
    #pragma unroll
    for (int i = 0; i < 4; i++) {
        int idx4 = i * 256 + tid;
        wr_[i] = idx4 >> 4; wc4[i] = idx4 & 15;
        wdst[i] = swz4(wr_[i], wc4[i]) * 16;
    }

    float acc[2][4][4];
    #pragma unroll
    for (int s = 0; s < 2; s++)
        #pragma unroll
        for (int nt = 0; nt < 4; nt++)
            #pragma unroll
            for (int i = 0; i < 4; i++) acc[s][nt][i] = 0.f;

    float sum8[8], sq8[8];
    #pragma unroll
    for (int i = 0; i < 8; i++) { sum8[i] = 0.f; sq8[i] = 0.f; }

    // ---- pass-1 staging: x chunk + gw chunk into buffer b ----
    auto stage1 = [&](int c, int b) {
        const uint32_t xb = sbase + SX_OFF(b) * 4;
        const uint32_t wb = sbase + SW_OFF(b) * 4;
        #pragma unroll
        for (int i = 0; i < 8; i++)
            CPA16(xb + xdst[i], xg + (size_t)xt[i] * (D_DIM / 4) + c * 16 + xc4[i]);
        #pragma unroll
        for (int i = 0; i < 4; i++)
            CPA16(wb + wdst[i], gwg + (size_t)wr_[i] * (D_DIM / 4) + c * 16 + wc4[i]);
        CPC();
    };

    // ===================== Pass 1: stats + G = x @ gw^T =====================
    stage1(0, 0);
    stage1(1, 1);

    for (int c = 0; c < NCHUNK; c++) {
        const int b = c & 1;
        if (c < NCHUNK - 1) { CPW(1); } else { CPW(0); }
        __syncthreads();

        const float*  bX  = smem + SX_OFF(b);
        const float*  bW  = smem + SW_OFF(b);
        const float4* bX4 = reinterpret_cast<const float4*>(bX);

        // stats from smem
        #pragma unroll
        for (int i = 0; i < 8; i++) {
            float4 v = bX4[swz4(xt[i], xc4[i])];
            sum8[i] += v.x + v.y + v.z + v.w;
            sq8[i]  += v.x * v.x + v.y * v.y + v.z * v.z + v.w * v.w;
        }

        #pragma unroll
        for (int ks = 0; ks < 8; ks++) {
            int kb = ks * 8 + (lane & 3);
            unsigned a[2][4];
            #pragma unroll
            for (int s = 0; s < 2; s++) {
                int r0 = mg * 32 + s * 16 + (lane >> 2);
                a[s][0] = __float_as_uint(bX[swzf(r0,     kb)]);
                a[s][1] = __float_as_uint(bX[swzf(r0 + 8, kb)]);
                a[s][2] = __float_as_uint(bX[swzf(r0,     kb + 4)]);
                a[s][3] = __float_as_uint(bX[swzf(r0 + 8, kb + 4)]);
            }
            #pragma unroll
            for (int nt = 0; nt < 4; nt++) {
                int n = (ng * 4 + nt) * 8 + (lane >> 2);
                unsigned bb[2];
                bb[0] = __float_as_uint(bW[swzf(n, kb)]);
                bb[1] = __float_as_uint(bW[swzf(n, kb + 4)]);
                mma_tf32(acc[0][nt], a[0], bb);
                mma_tf32(acc[1][nt], a[1], bb);
            }
        }
        __syncthreads();
        if (c + 2 < NCHUNK) stage1(c + 2, b);
    }

    // ===================== stats finalize (scratch in sW buffers) =====================
    float* sWf = smem + SW_OFF(0);   // 8192 floats available
    #pragma unroll
    for (int i = 0; i < 8; i++) {
        sWf[i * 256 + tid]        = sum8[i];
        sWf[2048 + i * 256 + tid] = sq8[i];
    }
    __syncthreads();

    float* sMu = sWf + 4096;          // [128] mu, [128] rstd
    if (tid < TOK_TILE) {
        int i    = tid >> 4;
        int base = (tid & 15) * 16;
        float s = 0.f, q = 0.f;
        #pragma unroll
        for (int j = 0; j < 16; j++) {
            s += sWf[i * 256 + base + j];
            q += sWf[2048 + i * 256 + base + j];
        }
        float mu  = s * (1.0f / (float)D_DIM);
        float var = q * (1.0f / (float)D_DIM) - mu * mu;
        sMu[tid]            = mu;
        sMu[TOK_TILE + tid] = rsqrtf(var + EPS);
    }
    __syncthreads();

    // ===================== down = relu(rstd*(G - mu*C1) + C2) -> sX buffer 0 =====================
    float* sDown = smem + SX_OFF(0);
    #pragma unroll
    for (int s = 0; s < 2; s++)
        #pragma unroll
        for (int nt = 0; nt < 4; nt++)
            #pragma unroll
            for (int i = 0; i < 4; i++) {
                int t = mg * 32 + s * 16 + (lane >> 2) + ((i >> 1) << 3);
                int r = (ng * 4 + nt) * 8 + 2 * (lane & 3) + (i & 1);
                float mu_t = sMu[t];
                float rs_t = sMu[TOK_TILE + t];
                float dv = rs_t * (acc[s][nt][i] - mu_t * g_C1[r]) + g_C2[r];
                sDown[swzf(t, r)] = fmaxf(dv, 0.f);
            }
    __syncthreads();   // mu/scratch dead; safe to stage wu into sW buffers

    // ---- pass-2 staging: wu chunk into buffer b ----
    auto stage2 = [&](int c, int b) {
        const uint32_t wb = sbase + SW_OFF(b) * 4;
        #pragma unroll
        for (int i = 0; i < 4; i++)
            CPA16(wb + wdst[i], wug + (size_t)(c * DC + wr_[i]) * (R_DIM / 4) + wc4[i]);
        CPC();
    };

    // ===================== Pass 2: up = down @ w_up^T; out = x + scale*(up + b_up) =====================
    stage2(0, 0);
    stage2(1, 1);

    for (int c = 0; c < NCHUNK; c++) {
        const int b = c & 1;
        if (c < NCHUNK - 1) { CPW(1); } else { CPW(0); }
        __syncthreads();

        const float* bW = smem + SW_OFF(b);

        float a2[2][4][4];
        #pragma unroll
        for (int s = 0; s < 2; s++)
            #pragma unroll
            for (int nt = 0; nt < 4; nt++)
                #pragma unroll
                for (int i = 0; i < 4; i++) a2[s][nt][i] = 0.f;

        #pragma unroll
        for (int ks = 0; ks < 8; ks++) {
            int kb = ks * 8 + (lane & 3);
            unsigned a[2][4];
            #pragma unroll
            for (int s = 0; s < 2; s++) {
                int r0 = mg * 32 + s * 16 + (lane >> 2);
                a[s][0] = __float_as_uint(sDown[swzf(r0,     kb)]);
                a[s][1] = __float_as_uint(sDown[swzf(r0 + 8, kb)]);
                a[s][2] = __float_as_uint(sDown[swzf(r0,     kb + 4)]);
                a[s][3] = __float_as_uint(sDown[swzf(r0 + 4 + 4, kb + 4)]);
            }
            // fix: a[s][3] row is r0+8 (same as a[1]); keep identical addressing
            #pragma unroll
            for (int s = 0; s < 2; s++) {
                int r0 = mg * 32 + s * 16 + (lane >> 2);
                a[s][3] = __float_as_uint(sDown[swzf(r0 + 8, kb + 4)]);
            }
            #pragma unroll
            for (int nt = 0; nt < 4; nt++) {
                int n = (ng * 4 + nt) * 8 + (lane >> 2);
                unsigned bb[2];
                bb[0] = __float_as_uint(bW[swzf(n, kb)]);
                bb[1] = __float_as_uint(bW[swzf(n, kb + 4)]);
                mma_tf32(a2[0][nt], a[0], bb);
                mma_tf32(a2[1][nt], a[1], bb);
            }
        }
        __syncthreads();            // everyone done with bW
        if (c + 2 < NCHUNK) stage2(c + 2, b);

        // epilogue: out = x + scale*(up + b_up)
        #pragma unroll
        for (int s = 0; s < 2; s++) {
            #pragma unroll
            for (int nt = 0; nt < 4; nt++) {
                int dl = (ng * 4 + nt) * 8 + 2 * (lane & 3);
                int d  = c * DC + dl;
                float2 bu = *reinterpret_cast<const float2*>(b_up + d);
                int trow = t0 + mg * 32 + s * 16 + (lane >> 2);

                float2 xv0 = *reinterpret_cast<const float2*>(x + (size_t)trow * D_DIM + d);
                float2 o0;
                o0.x = xv0.x + scaleV * (a2[s][nt][0] + bu.x);
                o0.y = xv0.y + scaleV * (a2[s][nt][1] + bu.y);
                *reinterpret_cast<float2*>(out + (size_t)trow * D_DIM + d) = o0;

                float2 xv8 = *reinterpret_cast<const float2*>(x + (size_t)(trow + 8) * D_DIM + d);
                float2 o8;
                o8.x = xv8.x + scaleV * (a2[s][nt][2] + bu.x);
                o8.y = xv8.y + scaleV * (a2[s][nt][3] + bu.y);
                *reinterpret_cast<float2*>(out + (size_t)(trow + 8) * D_DIM + d) = o8;
            }
        }
    }
}

// ---------------- launch ----------------

extern "C" void kernel_launch(void* const* d_in, const int* in_sizes, int n_in,
                              void* d_out, int out_size) {
    const float* x      = (const float*)d_in[0];
    const float* gamma  = (const float*)d_in[1];
    const float* beta   = (const float*)d_in[2];
    const float* w_down = (const float*)d_in[3];
    const float* b_down = (const float*)d_in[4];
    const float* w_up   = (const float*)d_in[5];
    const float* b_up   = (const float*)d_in[6];
    const float* scale  = (const float*)d_in[7];
    float* out          = (float*)d_out;

    cudaFuncSetAttribute(adapter_main, cudaFuncAttributeMaxDynamicSharedMemorySize, SMEM_BYTES);

    prep_kernel<<<R_DIM, 256>>>(w_down, gamma, beta, b_down);
    adapter_main<<<N_TOK / TOK_TILE, THREADS, SMEM_BYTES>>>(x, w_up, b_up, scale, out);
}

// round 4
// speedup vs baseline: 1.3525x; 1.3525x over previous
#include <cuda_runtime.h>
#include <cstdint>

// x [4,4096,2048] fp32 -> out fp32. R=64.
#define N_TOK    16384
#define D_DIM    2048
#define R_DIM    64
#define TOK_TILE 128
#define DC       64
#define NCHUNK   (D_DIM / DC)
#define EPS      1e-5f
#define THREADS  512
#define NSTAGE   3

// dynamic smem: sX[3][128*64] + sW[3][64*64]  = 3*8192 + 3*4096 floats = 144 KB
#define SX_OFF(b)  ((b) * 8192)
#define SW_OFF(b)  (24576 + (b) * 4096)
#define SMEM_FLOATS (24576 + 12288)
#define SMEM_BYTES  (SMEM_FLOATS * 4)

__device__ float g_C1[R_DIM];            // sum_d gw[r][d]
__device__ float g_C2[R_DIM];            // sum_d beta*w_down + b_down
__device__ float g_gw[R_DIM * D_DIM];    // tf32(gamma[d] * w_down[r][d])

// ---------------- helpers ----------------

__device__ __forceinline__ float to_tf32(float x) {
    unsigned u;
    asm("cvt.rna.tf32.f32 %0, %1;" : "=r"(u) : "f"(x));
    return __uint_as_float(u);
}
__device__ __forceinline__ int swz4(int row, int c4) { return row * 16 + ((c4 + row) & 15); }
__device__ __forceinline__ int swzf(int row, int col) {
    return (row << 6) + ((((col >> 2) + row) & 15) << 2) + (col & 3);
}
__device__ __forceinline__ void mma_tf32(float* c, const unsigned* a, const unsigned* b) {
    asm volatile(
        "mma.sync.aligned.m16n8k8.row.col.f32.tf32.tf32.f32 "
        "{%0,%1,%2,%3}, {%4,%5,%6,%7}, {%8,%9}, {%0,%1,%2,%3};"
        : "+f"(c[0]), "+f"(c[1]), "+f"(c[2]), "+f"(c[3])
        : "r"(a[0]), "r"(a[1]), "r"(a[2]), "r"(a[3]), "r"(b[0]), "r"(b[1]));
}

#define CPA16(dst_u32, src_ptr) \
    asm volatile("cp.async.cg.shared.global [%0], [%1], 16;" :: "r"(dst_u32), "l"(src_ptr))
#define CPC()  asm volatile("cp.async.commit_group;")
#define CPW2() asm volatile("cp.async.wait_group 2;")
#define CPW1() asm volatile("cp.async.wait_group 1;")
#define CPW0() asm volatile("cp.async.wait_group 0;")

__device__ __forceinline__ void cpw_tail(int c) {
    if (c < NCHUNK - 2)       { CPW2(); }
    else if (c == NCHUNK - 2) { CPW1(); }
    else                      { CPW0(); }
}

// ---------------- prep: gw = tf32(gamma*w_down), C1, C2 ----------------

__global__ void prep_kernel(const float* __restrict__ w_down,
                            const float* __restrict__ gamma,
                            const float* __restrict__ beta,
                            const float* __restrict__ b_down) {
    __shared__ float red1[8], red2[8];
    int r = blockIdx.x;
    float s1 = 0.f, s2 = 0.f;
    for (int d = threadIdx.x; d < D_DIM; d += 256) {
        float w = w_down[r * D_DIM + d];
        float gwv = to_tf32(gamma[d] * w);
        g_gw[r * D_DIM + d] = gwv;
        s1 += gwv;
        s2 += beta[d] * w;
    }
    #pragma unroll
    for (int o = 16; o; o >>= 1) {
        s1 += __shfl_down_sync(0xFFFFFFFFu, s1, o);
        s2 += __shfl_down_sync(0xFFFFFFFFu, s2, o);
    }
    if ((threadIdx.x & 31) == 0) { red1[threadIdx.x >> 5] = s1; red2[threadIdx.x >> 5] = s2; }
    __syncthreads();
    if (threadIdx.x == 0) {
        float t1 = 0.f, t2 = 0.f;
        #pragma unroll
        for (int i = 0; i < 8; i++) { t1 += red1[i]; t2 += red2[i]; }
        g_C1[r] = t1;
        g_C2[r] = t2 + b_down[r];
    }
}

// ---------------- main fused kernel ----------------

__global__ __launch_bounds__(THREADS, 1) void adapter_main(
    const float* __restrict__ x,
    const float* __restrict__ w_up,
    const float* __restrict__ b_up,
    const float* __restrict__ scale,
    float* __restrict__ out)
{
    extern __shared__ float smem[];
    const uint32_t sbase = (uint32_t)__cvta_generic_to_shared(smem);

    const int tid  = threadIdx.x;
    const int lane = tid & 31;
    const int wrp  = tid >> 5;          // 0..15
    const int mg   = wrp & 7;           // 16-token m-strip
    const int ng   = wrp >> 3;          // 32-col n-strip (0..1)
    const int t0   = blockIdx.x * TOK_TILE;
    const int tr0  = mg * 16 + (lane >> 2);

    const float scaleV = scale[0];

    const float4* __restrict__ xg  = reinterpret_cast<const float4*>(x) + (size_t)t0 * (D_DIM / 4);
    const float4* __restrict__ gwg = reinterpret_cast<const float4*>(g_gw);
    const float4* __restrict__ wug = reinterpret_cast<const float4*>(w_up);

    // staging coords: x 4 slots/thread, w 2 slots/thread
    int xt[4], xc4[4], xdst[4];
    #pragma unroll
    for (int i = 0; i < 4; i++) {
        int idx4 = i * THREADS + tid;
        xt[i] = idx4 >> 4; xc4[i] = idx4 & 15;
        xdst[i] = swz4(xt[i], xc4[i]) * 16;
    }
    int wr_[2], wc4[2], wdst[2];
    #pragma unroll
    for (int i = 0; i < 2; i++) {
        int idx4 = i * THREADS + tid;
        wr_[i] = idx4 >> 4; wc4[i] = idx4 & 15;
        wdst[i] = swz4(wr_[i], wc4[i]) * 16;
    }

    float acc[4][4];
    #pragma unroll
    for (int nt = 0; nt < 4; nt++)
        #pragma unroll
        for (int i = 0; i < 4; i++) acc[nt][i] = 0.f;

    float sum4[4], sq4[4];
    #pragma unroll
    for (int i = 0; i < 4; i++) { sum4[i] = 0.f; sq4[i] = 0.f; }

    auto stage1 = [&](int c, int b) {
        const uint32_t xb = sbase + SX_OFF(b) * 4;
        const uint32_t wb = sbase + SW_OFF(b) * 4;
        #pragma unroll
        for (int i = 0; i < 4; i++)
            CPA16(xb + xdst[i], xg + (size_t)xt[i] * (D_DIM / 4) + c * 16 + xc4[i]);
        #pragma unroll
        for (int i = 0; i < 2; i++)
            CPA16(wb + wdst[i], gwg + (size_t)wr_[i] * (D_DIM / 4) + c * 16 + wc4[i]);
        CPC();
    };

    // ===================== Pass 1: stats + G = x @ gw^T =====================
    stage1(0, 0); stage1(1, 1); stage1(2, 2);

    for (int c = 0; c < NCHUNK; c++) {
        const int b = c % NSTAGE;
        cpw_tail(c);
        __syncthreads();

        const float*  bX  = smem + SX_OFF(b);
        const float*  bW  = smem + SW_OFF(b);
        const float4* bX4 = reinterpret_cast<const float4*>(bX);

        // stats from smem (same slots this thread staged)
        #pragma unroll
        for (int i = 0; i < 4; i++) {
            float4 v = bX4[swz4(xt[i], xc4[i])];
            sum4[i] += v.x + v.y + v.z + v.w;
            sq4[i]  += v.x * v.x + v.y * v.y + v.z * v.z + v.w * v.w;
        }

        #pragma unroll
        for (int ks = 0; ks < 8; ks++) {
            int kb = ks * 8 + (lane & 3);
            unsigned a[4];
            a[0] = __float_as_uint(bX[swzf(tr0,     kb)]);
            a[1] = __float_as_uint(bX[swzf(tr0 + 8, kb)]);
            a[2] = __float_as_uint(bX[swzf(tr0,     kb + 4)]);
            a[3] = __float_as_uint(bX[swzf(tr0 + 8, kb + 4)]);
            #pragma unroll
            for (int nt = 0; nt < 4; nt++) {
                int n = ng * 32 + nt * 8 + (lane >> 2);
                unsigned bb[2];
                bb[0] = __float_as_uint(bW[swzf(n, kb)]);
                bb[1] = __float_as_uint(bW[swzf(n, kb + 4)]);
                mma_tf32(acc[nt], a, bb);
            }
        }
        __syncthreads();
        if (c + NSTAGE < NCHUNK) stage1(c + NSTAGE, b);
    }

    // ===================== stats finalize =====================
    // flat index idx4 = i*512+tid maps to token t = idx4>>4, slot j = idx4&15
    float* sWf = smem + SW_OFF(0);     // 12288 floats of scratch available
    #pragma unroll
    for (int i = 0; i < 4; i++) {
        int idx4 = i * THREADS + tid;
        sWf[idx4]        = sum4[i];
        sWf[2048 + idx4] = sq4[i];
    }
    __syncthreads();

    float* sMu = sWf + 4096;           // [128] mu, [128] rstd
    if (tid < TOK_TILE) {
        float s = 0.f, q = 0.f;
        #pragma unroll
        for (int j = 0; j < 16; j++) {
            s += sWf[tid * 16 + j];
            q += sWf[2048 + tid * 16 + j];
        }
        float mu  = s * (1.0f / (float)D_DIM);
        float var = q * (1.0f / (float)D_DIM) - mu * mu;
        sMu[tid]            = mu;
        sMu[TOK_TILE + tid] = rsqrtf(var + EPS);
    }
    __syncthreads();

    // ===================== down = relu(rstd*(G - mu*C1) + C2) -> sX buffer 0 =====================
    float* sDown = smem + SX_OFF(0);
    #pragma unroll
    for (int nt = 0; nt < 4; nt++)
        #pragma unroll
        for (int i = 0; i < 4; i++) {
            int t = mg * 16 + (lane >> 2) + ((i >> 1) << 3);
            int r = ng * 32 + nt * 8 + 2 * (lane & 3) + (i & 1);
            float dv = sMu[TOK_TILE + t] * (acc[nt][i] - sMu[t] * g_C1[r]) + g_C2[r];
            sDown[swzf(t, r)] = fmaxf(dv, 0.f);
        }
    __syncthreads();   // sMu dead after this; wu staging may overwrite sW area

    auto stage2 = [&](int c, int b) {
        const uint32_t wb = sbase + SW_OFF(b) * 4;
        #pragma unroll
        for (int i = 0; i < 2; i++)
            CPA16(wb + wdst[i], wug + (size_t)(c * DC + wr_[i]) * (R_DIM / 4) + wc4[i]);
        CPC();
    };

    // ===================== Pass 2: up = down @ w_up^T; out = x + scale*(up + b_up) =====================
    stage2(0, 0); stage2(1, 1); stage2(2, 2);

    for (int c = 0; c < NCHUNK; c++) {
        const int b = c % NSTAGE;
        cpw_tail(c);
        __syncthreads();

        const float* bW = smem + SW_OFF(b);

        float a2[4][4];
        #pragma unroll
        for (int nt = 0; nt < 4; nt++)
            #pragma unroll
            for (int i = 0; i < 4; i++) a2[nt][i] = 0.f;

        #pragma unroll
        for (int ks = 0; ks < 8; ks++) {
            int kb = ks * 8 + (lane & 3);
            unsigned a[4];
            a[0] = __float_as_uint(sDown[swzf(tr0,     kb)]);
            a[1] = __float_as_uint(sDown[swzf(tr0 + 8, kb)]);
            a[2] = __float_as_uint(sDown[swzf(tr0,     kb + 4)]);
            a[3] = __float_as_uint(sDown[swzf(tr0 + 8, kb + 4)]);
            #pragma unroll
            for (int nt = 0; nt < 4; nt++) {
                int n = ng * 32 + nt * 8 + (lane >> 2);
                unsigned bb[2];
                bb[0] = __float_as_uint(bW[swzf(n, kb)]);
                bb[1] = __float_as_uint(bW[swzf(n, kb + 4)]);
                mma_tf32(a2[nt], a, bb);
            }
        }
        __syncthreads();            // done with bW
        if (c + NSTAGE < NCHUNK) stage2(c + NSTAGE, b);

        // epilogue: out = x + scale*(up + b_up)
        #pragma unroll
        for (int nt = 0; nt < 4; nt++) {
            int dl = ng * 32 + nt * 8 + 2 * (lane & 3);
            int d  = c * DC + dl;
            float2 bu = *reinterpret_cast<const float2*>(b_up + d);
            int trow = t0 + mg * 16 + (lane >> 2);

            float2 xv0 = *reinterpret_cast<const float2*>(x + (size_t)trow * D_DIM + d);
            float2 o0;
            o0.x = xv0.x + scaleV * (a2[nt][0] + bu.x);
            o0.y = xv0.y + scaleV * (a2[nt][1] + bu.y);
            *reinterpret_cast<float2*>(out + (size_t)trow * D_DIM + d) = o0;

            float2 xv8 = *reinterpret_cast<const float2*>(x + (size_t)(trow + 8) * D_DIM + d);
            float2 o8;
            o8.x = xv8.x + scaleV * (a2[nt][2] + bu.x);
            o8.y = xv8.y + scaleV * (a2[nt][3] + bu.y);
            *reinterpret_cast<float2*>(out + (size_t)(trow + 8) * D_DIM + d) = o8;
        }
    }
}

// ---------------- launch ----------------

extern "C" void kernel_launch(void* const* d_in, const int* in_sizes, int n_in,
                              void* d_out, int out_size) {
    const float* x      = (const float*)d_in[0];
    const float* gamma  = (const float*)d_in[1];
    const float* beta   = (const float*)d_in[2];
    const float* w_down = (const float*)d_in[3];
    const float* b_down = (const float*)d_in[4];
    const float* w_up   = (const float*)d_in[5];
    const float* b_up   = (const float*)d_in[6];
    const float* scale  = (const float*)d_in[7];
    float* out          = (float*)d_out;

    cudaFuncSetAttribute(adapter_main, cudaFuncAttributeMaxDynamicSharedMemorySize, SMEM_BYTES);

    prep_kernel<<<R_DIM, 256>>>(w_down, gamma, beta, b_down);
    adapter_main<<<N_TOK / TOK_TILE, THREADS, SMEM_BYTES>>>(x, w_up, b_up, scale, out);
}